// round 16
// baseline (speedup 1.0000x reference)
#include <cuda_runtime.h>
#include <cuda_fp16.h>
#include <cstdint>

#define NATOMS 25000
#define NPAIRS 500000
#define NBLKA 7813
#define NBLKB 3907

__device__ __align__(16) float g_h[NATOMS * 64];
__device__ __align__(16) float g_p[NATOMS * 64];
__device__ __align__(16) float g_newp[NATOMS * 64];
__device__ __align__(16) float g_u[NATOMS * 64];
__device__ __align__(16) float g_v[NATOMS * 64];
__device__ __align__(16) uint32_t g_w2H[8192], g_w2L[8192];
__device__ __align__(16) uint32_t g_wi1H[2048], g_wi1L[2048];
__device__ __align__(16) uint32_t g_wi2H[2048], g_wi2L[2048];
__device__ __align__(16) uint32_t g_intH[(NPAIRS + 128) * 32];
__device__ __align__(16) uint32_t g_intL[(NPAIRS + 128) * 32];

// slim tanh: 1 - 2*rcp(2^(2x*log2e)+1); 5 instr, inf-safe (~1e-7 rel err)
__device__ __forceinline__ float tfast(float x) {
    float e, r;
    asm("ex2.approx.f32 %0, %1;" : "=f"(e) : "f"(x * 2.885390081777927f));
    asm("rcp.approx.f32 %0, %1;" : "=f"(r) : "f"(e + 1.f));
    return fmaf(-2.f, r, 1.f);
}

__device__ __forceinline__ void split2(float x0, float x1, uint32_t& H, uint32_t& L) {
    __half h0 = __float2half_rn(x0), h1 = __float2half_rn(x1);
    float r0 = x0 - __half2float(h0);
    float r1 = x1 - __half2float(h1);
    __half2 hh = __halves2half2(h0, h1);
    __half2 ll = __halves2half2(__float2half_rn(r0), __float2half_rn(r1));
    H = *reinterpret_cast<uint32_t*>(&hh);
    L = *reinterpret_cast<uint32_t*>(&ll);
}

__device__ __forceinline__ void mma16(float* d, uint32_t a0, uint32_t a1, uint32_t a2,
                                      uint32_t a3, uint32_t b0, uint32_t b1) {
    asm volatile("mma.sync.aligned.m16n8k16.row.col.f32.f16.f16.f32 "
        "{%0,%1,%2,%3}, {%4,%5,%6,%7}, {%8,%9}, {%0,%1,%2,%3};"
        : "+f"(d[0]), "+f"(d[1]), "+f"(d[2]), "+f"(d[3])
        : "r"(a0), "r"(a1), "r"(a2), "r"(a3), "r"(b0), "r"(b1));
}

__device__ __forceinline__ void red4(float* p, float a, float b, float c, float d) {
    asm volatile("red.global.add.v4.f32 [%0], {%1,%2,%3,%4};"
        :: "l"(p), "f"(a), "f"(b), "f"(c), "f"(d) : "memory");
}

// 3-term fp16 warp GEMM: 32 rows x 32 cols, K=16*KC.
// A operands MUST be smem; W may be smem or global (warp-uniform 8B loads).
template<int KC>
__device__ __forceinline__ void gemm16(const uint32_t* __restrict__ AH, const uint32_t* __restrict__ AL,
        const uint32_t* __restrict__ WH, const uint32_t* __restrict__ WL,
        int r0, int tileBase, int lane, float acc[2][4][4])
{
    const int tig = lane & 3, gid = lane >> 2;
    const int sw = gid << 2;
#pragma unroll
    for (int kc = 0; kc < KC; kc++) {
        int k0 = (kc * 8 + tig) ^ sw;
        int k1 = (kc * 8 + tig + 4) ^ sw;
        uint32_t ah[2][4], al[2][4];
#pragma unroll
        for (int mt = 0; mt < 2; mt++) {
            const uint32_t* bh = AH + (r0 + mt * 16 + gid) * 32;
            const uint32_t* bl = AL + (r0 + mt * 16 + gid) * 32;
            ah[mt][0] = bh[k0]; ah[mt][1] = bh[256 + k0];
            ah[mt][2] = bh[k1]; ah[mt][3] = bh[256 + k1];
            al[mt][0] = bl[k0]; al[mt][1] = bl[256 + k0];
            al[mt][2] = bl[k1]; al[mt][3] = bl[256 + k1];
        }
#pragma unroll
        for (int nt = 0; nt < 4; nt++) {
            int wi = ((tileBase + nt) * KC + kc) * 64 + lane * 2;
            uint2 bh = *(const uint2*)(WH + wi);
            uint2 bl = *(const uint2*)(WL + wi);
#pragma unroll
            for (int mt = 0; mt < 2; mt++) {
                mma16(acc[mt][nt], ah[mt][0], ah[mt][1], ah[mt][2], ah[mt][3], bh.x, bh.y);
                mma16(acc[mt][nt], ah[mt][0], ah[mt][1], ah[mt][2], ah[mt][3], bl.x, bl.y);
                mma16(acc[mt][nt], al[mt][0], al[mt][1], al[mt][2], al[mt][3], bh.x, bh.y);
            }
        }
    }
}

// ---------------------------------------------------------------------------
__global__ void prep_kernel(const float* __restrict__ w2,
                            const float* __restrict__ wi1, const float* __restrict__ wi2) {
    int tid = blockIdx.x * blockDim.x + threadIdx.x;
    int stride = gridDim.x * blockDim.x;
    for (int idx = tid; idx < 4096; idx += stride) {
        int lane = idx & 31, kc = (idx >> 5) & 3, t = idx >> 7;
        int n = t * 8 + (lane >> 2);
        int k0 = kc * 16 + 2 * (lane & 3);
        int o = (t * 4 + kc) * 64 + lane * 2;
        uint32_t h, l;
        split2(w2[k0 * 256 + n], w2[(k0 + 1) * 256 + n], h, l);
        g_w2H[o] = h; g_w2L[o] = l;
        split2(w2[(k0 + 8) * 256 + n], w2[(k0 + 9) * 256 + n], h, l);
        g_w2H[o + 1] = h; g_w2L[o + 1] = l;
    }
    for (int idx = tid; idx < 1024; idx += stride) {
        int lane = idx & 31, kc = (idx >> 5) & 3, t = idx >> 7;
        int n = t * 8 + (lane >> 2);
        int k0 = kc * 16 + 2 * (lane & 3);
        int o = (t * 4 + kc) * 64 + lane * 2;
        uint32_t h, l;
        split2(wi1[k0 * 64 + n], wi1[(k0 + 1) * 64 + n], h, l);
        g_wi1H[o] = h; g_wi1L[o] = l;
        split2(wi1[(k0 + 8) * 64 + n], wi1[(k0 + 9) * 64 + n], h, l);
        g_wi1H[o + 1] = h; g_wi1L[o + 1] = l;
        split2(wi2[k0 * 64 + n], wi2[(k0 + 1) * 64 + n], h, l);
        g_wi2H[o] = h; g_wi2L[o] = l;
        split2(wi2[(k0 + 8) * 64 + n], wi2[(k0 + 9) * 64 + n], h, l);
        g_wi2H[o + 1] = h; g_wi2L[o + 1] = l;
    }
    for (int i = tid; i < 4096; i += stride) {
        g_intH[NPAIRS * 32 + i] = 0;
        g_intL[NPAIRS * 32 + i] = 0;
    }
}

// ---------------------------------------------------------------------------
// pairA: persistent, 64 pairs/iter, 3 CTAs/SM, SOFTWARE-PIPELINED:
// gather(iter n+1) -> ww1[buf^1] overlaps GEMM(iter n) from ww1[buf].
// INT written uint4-direct to global from the epilogue (no staging, 1 barrier).
// ---------------------------------------------------------------------------
#define A_W2H   0        // 8192 words
#define A_WW1H0 8192     // 2048
#define A_WW1L0 10240    // 2048
#define A_WW1H1 12288    // 2048
#define A_WW1L1 14336    // 2048
#define A_BAS0  16384    // 256 floats
#define A_BAS1  16640    // 256 floats
#define A_B2    16896    // 256 floats
#define A_SMEM_BYTES (17152 * 4)

__device__ __forceinline__ void gatherA(uint32_t* smw, int pairbase,
        int bufH, int bufL, int bufBAS,
        const int* __restrict__ ind2, const float* __restrict__ basis, int tid) {
    float* smf = (float*)smw;
    if (tid < 64) {
        int p = pairbase + tid;
        float4 bs = make_float4(0.f, 0.f, 0.f, 0.f);
        if (p < NPAIRS) bs = ((const float4*)basis)[p];
        ((float4*)(smf + bufBAS))[tid] = bs;
    }
#pragma unroll
    for (int r = 0; r < 8; r++) {
        int idx = tid + r * 256;
        int row = idx >> 5, kp = idx & 31;
        int gp = pairbase + row;
        float x0 = 0.f, x1 = 0.f;
        if (gp < NPAIRS) {
            int ai = ind2[2 * gp], aj = ind2[2 * gp + 1];
            float2 u = *(const float2*)&g_u[ai * 64 + 2 * kp];
            float2 v = *(const float2*)&g_v[aj * 64 + 2 * kp];
            x0 = tfast(u.x + v.x);
            x1 = tfast(u.y + v.y);
        }
        uint32_t H, L; split2(x0, x1, H, L);
        int o = row * 32 + (kp ^ ((row & 7) << 2));
        smw[bufH + o] = H; smw[bufL + o] = L;
    }
}

__global__ __launch_bounds__(256, 3) void pairA(
    const int* __restrict__ ind2, const float* __restrict__ basis,
    const float* __restrict__ b2)
{
    extern __shared__ uint32_t smw[];
    float* smf = (float*)smw;
    const int tid = threadIdx.x;

    for (int i = tid; i < 2048; i += 256) ((uint4*)(smw + A_W2H))[i] = ((const uint4*)g_w2H)[i];
    if (tid < 128) { smf[A_B2 + tid] = b2[tid]; smf[A_B2 + 128 + tid] = b2[128 + tid]; }

    const int lane = tid & 31, w = tid >> 5;
    const int rg = w & 1, cg = w >> 1;       // 2 row-groups x 4 col-groups
    const int r0 = rg * 32;
    const int tig = lane & 3, gid = lane >> 2;

    // prologue: gather first block into buffer 0
    int blk0 = blockIdx.x;
    if (blk0 < NBLKA)
        gatherA(smw, blk0 * 64, A_WW1H0, A_WW1L0, A_BAS0, ind2, basis, tid);
    __syncthreads();

    int buf = 0;
    for (int blk = blk0; blk < NBLKA; blk += gridDim.x) {
        const int pairbase = blk * 64;
        const int curH  = buf ? A_WW1H1 : A_WW1H0;
        const int curL  = buf ? A_WW1L1 : A_WW1L0;
        const int curB  = buf ? A_BAS1 : A_BAS0;
        const int nxtH  = buf ? A_WW1H0 : A_WW1H1;
        const int nxtL  = buf ? A_WW1L0 : A_WW1L1;
        const int nxtB  = buf ? A_BAS0 : A_BAS1;

        // (a) prefetch-gather next block into the other buffer (LDGs overlap GEMM)
        int nblk = blk + gridDim.x;
        if (nblk < NBLKA)
            gatherA(smw, nblk * 64, nxtH, nxtL, nxtB, ind2, basis, tid);

        // (b) GEMM + epilogue on current buffer, INT direct to global
        float4 bsv[4];
#pragma unroll
        for (int q = 0; q < 4; q++) bsv[q] = ((float4*)(smf + curB))[r0 + gid + q * 8];
#pragma unroll 1
        for (int j = 0; j < 2; j++) {
            int g = cg + 4 * j;
            float acc[2][4][4];
#pragma unroll
            for (int a = 0; a < 2; a++)
#pragma unroll
                for (int b = 0; b < 4; b++)
#pragma unroll
                    for (int q = 0; q < 4; q++) acc[a][b][q] = 0.f;
            gemm16<4>(smw + curH, smw + curL, smw + A_W2H, g_w2L, r0, g * 4, lane, acc);

            uint32_t hL[4], lL[4], hH[4], lH[4];
#pragma unroll
            for (int mt = 0; mt < 2; mt++) {
#pragma unroll
                for (int nt = 0; nt < 4; nt++) {
                    int c0 = g * 32 + nt * 8 + 2 * tig;
                    float b20 = smf[A_B2 + c0], b21 = smf[A_B2 + c0 + 1];
                    float4 bL = bsv[mt * 2], bH = bsv[mt * 2 + 1];
                    float cL0 = (tig & 1) ? bL.z : bL.x, cL1 = (tig & 1) ? bL.w : bL.y;
                    float cH0 = (tig & 1) ? bH.z : bH.x, cH1 = (tig & 1) ? bH.w : bH.y;
                    float pl = tfast(acc[mt][nt][0] + b20) * cL0 + tfast(acc[mt][nt][1] + b21) * cL1;
                    float ph = tfast(acc[mt][nt][2] + b20) * cH0 + tfast(acc[mt][nt][3] + b21) * cH1;
                    pl += __shfl_xor_sync(0xffffffffu, pl, 1);
                    ph += __shfl_xor_sync(0xffffffffu, ph, 1);
                    float pl2 = __shfl_xor_sync(0xffffffffu, pl, 2);
                    float ph2 = __shfl_xor_sync(0xffffffffu, ph, 2);
                    split2(pl, pl2, hL[nt], lL[nt]);
                    split2(ph, ph2, hH[nt], lH[nt]);
                }
                if (tig == 0) {
                    int rL = r0 + mt * 16 + gid, rH = rL + 8;
                    int oL = (pairbase + rL) * 32 + ((g * 4) ^ (gid << 2));
                    int oH = (pairbase + rH) * 32 + ((g * 4) ^ (gid << 2));
                    *(uint4*)(g_intH + oL) = make_uint4(hL[0], hL[1], hL[2], hL[3]);
                    *(uint4*)(g_intL + oL) = make_uint4(lL[0], lL[1], lL[2], lL[3]);
                    *(uint4*)(g_intH + oH) = make_uint4(hH[0], hH[1], hH[2], hH[3]);
                    *(uint4*)(g_intL + oH) = make_uint4(lH[0], lH[1], lH[2], lH[3]);
                }
            }
        }
        __syncthreads();   // next-buffer gather visible; current-buffer reads done
        buf ^= 1;
    }
}

// ---------------------------------------------------------------------------
// pairB: persistent, 128 pairs/iter, 3 CTAs/SM. inter -> t1 -> t2 -> red.v4.
// ---------------------------------------------------------------------------
#define B_R0   0
#define B_WI1H 8704
#define B_WI1L 10752
#define B_WI2H 12800
#define B_WI2L 14848
#define B_IDX  16896
#define B_SMEM_BYTES (17024 * 4)

__global__ __launch_bounds__(256, 3) void pairB(const int* __restrict__ ind2)
{
    extern __shared__ uint32_t smw[];
    float* smf = (float*)smw;
    const int tid = threadIdx.x;

    for (int i = tid; i < 512; i += 256) {
        ((uint4*)(smw + B_WI1H))[i] = ((const uint4*)g_wi1H)[i];
        ((uint4*)(smw + B_WI1L))[i] = ((const uint4*)g_wi1L)[i];
        ((uint4*)(smw + B_WI2H))[i] = ((const uint4*)g_wi2H)[i];
        ((uint4*)(smw + B_WI2L))[i] = ((const uint4*)g_wi2L)[i];
    }

    const int lane = tid & 31, w = tid >> 5;
    const int rg = w & 3, cg = w >> 2;
    const int r0 = rg * 32;
    const int tig = lane & 3, gid = lane >> 2;

    for (int blk = blockIdx.x; blk < NBLKB; blk += gridDim.x) {
        const int pairbase = blk * 128;
        __syncthreads();

        for (int i = tid; i < 1024; i += 256) {
            ((uint4*)(smw + B_R0))[i] = ((const uint4*)(g_intH + pairbase * 32))[i];
            ((uint4*)(smw + B_R0 + 4096))[i] = ((const uint4*)(g_intL + pairbase * 32))[i];
        }
        if (tid < 128) {
            int p = pairbase + tid;
            ((int*)(smw + B_IDX))[tid] = (p < NPAIRS) ? ind2[2 * p] : -1;
        }
        __syncthreads();

        float acc[2][4][4];
#pragma unroll
        for (int a = 0; a < 2; a++)
#pragma unroll
            for (int b = 0; b < 4; b++)
#pragma unroll
                for (int q = 0; q < 4; q++) acc[a][b][q] = 0.f;
        gemm16<4>(smw + B_R0, smw + B_R0 + 4096, smw + B_WI1H, smw + B_WI1L, r0, cg * 4, lane, acc);
        __syncthreads();
#pragma unroll
        for (int mt = 0; mt < 2; mt++)
#pragma unroll
            for (int nt = 0; nt < 4; nt++) {
                int kp = cg * 16 + nt * 4 + tig;
                int rL = r0 + mt * 16 + gid, rH = rL + 8;
                uint32_t H, L;
                split2(tfast(acc[mt][nt][0]), tfast(acc[mt][nt][1]), H, L);
                int o = rL * 32 + (kp ^ (gid << 2));
                smw[B_R0 + o] = H; smw[B_R0 + 4096 + o] = L;
                split2(tfast(acc[mt][nt][2]), tfast(acc[mt][nt][3]), H, L);
                o = rH * 32 + (kp ^ (gid << 2));
                smw[B_R0 + o] = H; smw[B_R0 + 4096 + o] = L;
            }
        __syncthreads();

#pragma unroll
        for (int a = 0; a < 2; a++)
#pragma unroll
            for (int b = 0; b < 4; b++)
#pragma unroll
                for (int q = 0; q < 4; q++) acc[a][b][q] = 0.f;
        gemm16<4>(smw + B_R0, smw + B_R0 + 4096, smw + B_WI2H, smw + B_WI2L, r0, cg * 4, lane, acc);
        __syncthreads();
#pragma unroll
        for (int mt = 0; mt < 2; mt++)
#pragma unroll
            for (int nt = 0; nt < 4; nt++) {
                int c0 = cg * 32 + nt * 8 + 2 * tig;
                int rL = r0 + mt * 16 + gid, rH = rL + 8;
                float2 v;
                v.x = tfast(acc[mt][nt][0]); v.y = tfast(acc[mt][nt][1]);
                *(float2*)&smf[rL * 68 + c0] = v;
                v.x = tfast(acc[mt][nt][2]); v.y = tfast(acc[mt][nt][3]);
                *(float2*)&smf[rH * 68 + c0] = v;
            }
        __syncthreads();

        const int* idxI = (const int*)(smw + B_IDX);
#pragma unroll
        for (int r = 0; r < 8; r++) {
            int i = tid + r * 256;
            int row = i >> 4, seg = i & 15;
            int a = idxI[row];
            if (a >= 0) {
                float4 v = *(float4*)&smf[row * 68 + seg * 4];
                red4(g_newp + a * 64 + seg * 4, v.x, v.y, v.z, v.w);
            }
        }
    }
}

// ---------------------------------------------------------------------------
__device__ __forceinline__ void mm4(float acc[4][4], const float* __restrict__ A, int lda,
                                    const float* __restrict__ W, int ldw, int k4) {
    float4 w0 = *(const float4*)(W + (k4 * 4 + 0) * ldw);
    float4 w1 = *(const float4*)(W + (k4 * 4 + 1) * ldw);
    float4 w2 = *(const float4*)(W + (k4 * 4 + 2) * ldw);
    float4 w3 = *(const float4*)(W + (k4 * 4 + 3) * ldw);
#pragma unroll
    for (int i = 0; i < 4; i++) {
        float4 a = *(const float4*)(A + i * lda + k4 * 4);
        acc[i][0] = fmaf(a.x, w0.x, fmaf(a.y, w1.x, fmaf(a.z, w2.x, fmaf(a.w, w3.x, acc[i][0]))));
        acc[i][1] = fmaf(a.x, w0.y, fmaf(a.y, w1.y, fmaf(a.z, w2.y, fmaf(a.w, w3.y, acc[i][1]))));
        acc[i][2] = fmaf(a.x, w0.z, fmaf(a.y, w1.z, fmaf(a.z, w2.z, fmaf(a.w, w3.z, acc[i][2]))));
        acc[i][3] = fmaf(a.x, w0.w, fmaf(a.y, w1.w, fmaf(a.z, w2.w, fmaf(a.w, w3.w, acc[i][3]))));
    }
}

#define PRE_SMEM_BYTES (12416 * 4)
__global__ __launch_bounds__(256, 1) void atom_pre_kernel(
    const float* __restrict__ prop, int d,
    const float* __restrict__ w1, const float* __restrict__ b1,
    const float* __restrict__ w2, const float* __restrict__ b2,
    const float* __restrict__ piw1, const float* __restrict__ pib1)
{
    extern __shared__ float sm[];
    float* sSrc = sm;
    float* sW   = sm + 4096;
    float* sH   = sm + 8192;
    float* sB   = sm + 12288;
    float* sB1  = sm + 12352;

    const int tid = threadIdx.x;
    const int abase = blockIdx.x * 64;
    const int K0 = (d == 0) ? 16 : 64;
    const int kq = K0 >> 2;
    const float* src = (d == 0) ? prop : g_p;

    for (int i = tid; i < K0 * 64; i += 256) sW[i] = w1[i];
    if (tid < 64) { sB[tid] = b1[tid]; sB1[tid] = pib1[tid]; }
    for (int i = tid; i < 64 * kq; i += 256) {
        int a = i / kq, seg = i % kq;
        float4 v = make_float4(0.f, 0.f, 0.f, 0.f);
        if (abase + a < NATOMS) v = ((const float4*)src)[(abase + a) * kq + seg];
        *(float4*)(sSrc + a * 64 + seg * 4) = v;
    }
    for (int i = tid; i < 1024; i += 256) {
        int a = i >> 4;
        if (abase + a < NATOMS)
            ((float4*)g_newp)[(abase + a) * 16 + (i & 15)] = make_float4(0.f, 0.f, 0.f, 0.f);
    }
    __syncthreads();

    const int ar = tid >> 4, cr = tid & 15;
    {
        float acc[4][4];
#pragma unroll
        for (int i = 0; i < 4; i++) { acc[i][0] = acc[i][1] = acc[i][2] = acc[i][3] = 0.f; }
        const float* A = sSrc + ar * 4 * 64;
        const float* W = sW + cr * 4;
        for (int k4 = 0; k4 < kq; k4++) mm4(acc, A, 64, W, 64, k4);
        float4 bv = *(const float4*)(sB + cr * 4);
#pragma unroll
        for (int i = 0; i < 4; i++) {
            float4 v;
            v.x = tfast(acc[i][0] + bv.x); v.y = tfast(acc[i][1] + bv.y);
            v.z = tfast(acc[i][2] + bv.z); v.w = tfast(acc[i][3] + bv.w);
            *(float4*)(sH + (ar * 4 + i) * 64 + cr * 4) = v;
        }
    }
    __syncthreads();
    for (int i = tid; i < 4096; i += 256) sW[i] = w2[i];
    if (tid < 64) sB[tid] = b2[tid];
    __syncthreads();
    {
        float acc[4][4];
#pragma unroll
        for (int i = 0; i < 4; i++) { acc[i][0] = acc[i][1] = acc[i][2] = acc[i][3] = 0.f; }
        const float* A = sH + ar * 4 * 64;
        const float* W = sW + cr * 4;
#pragma unroll 4
        for (int k4 = 0; k4 < 16; k4++) mm4(acc, A, 64, W, 64, k4);
        float4 bv = *(const float4*)(sB + cr * 4);
#pragma unroll
        for (int i = 0; i < 4; i++) {
            int a = abase + ar * 4 + i;
            float4 v;
            v.x = tfast(acc[i][0] + bv.x); v.y = tfast(acc[i][1] + bv.y);
            v.z = tfast(acc[i][2] + bv.z); v.w = tfast(acc[i][3] + bv.w);
            if (a < NATOMS) ((float4*)g_h)[a * 16 + cr] = v;
            *(float4*)(sSrc + (ar * 4 + i) * 64 + cr * 4) = v;
        }
    }
    __syncthreads();

    for (int i = tid; i < 4096; i += 256) sW[i] = piw1[i];
    __syncthreads();
    {
        float acc[4][4];
#pragma unroll
        for (int i = 0; i < 4; i++) { acc[i][0] = acc[i][1] = acc[i][2] = acc[i][3] = 0.f; }
        const float* A = sSrc + ar * 4 * 64;
        const float* W = sW + cr * 4;
#pragma unroll 4
        for (int k4 = 0; k4 < 16; k4++) mm4(acc, A, 64, W, 64, k4);
        float4 bv = *(const float4*)(sB1 + cr * 4);
#pragma unroll
        for (int i = 0; i < 4; i++) {
            int a = abase + ar * 4 + i;
            if (a < NATOMS) {
                float4 v;
                v.x = acc[i][0] + bv.x; v.y = acc[i][1] + bv.y;
                v.z = acc[i][2] + bv.z; v.w = acc[i][3] + bv.w;
                ((float4*)g_u)[a * 16 + cr] = v;
            }
        }
    }
    __syncthreads();

    for (int i = tid; i < 4096; i += 256) sW[i] = piw1[4096 + i];
    __syncthreads();
    {
        float acc[4][4];
#pragma unroll
        for (int i = 0; i < 4; i++) { acc[i][0] = acc[i][1] = acc[i][2] = acc[i][3] = 0.f; }
        const float* A = sSrc + ar * 4 * 64;
        const float* W = sW + cr * 4;
#pragma unroll 4
        for (int k4 = 0; k4 < 16; k4++) mm4(acc, A, 64, W, 64, k4);
#pragma unroll
        for (int i = 0; i < 4; i++) {
            int a = abase + ar * 4 + i;
            if (a < NATOMS) {
                float4 v = make_float4(acc[i][0], acc[i][1], acc[i][2], acc[i][3]);
                ((float4*)g_v)[a * 16 + cr] = v;
            }
        }
    }
}

#define POST_SMEM_BYTES (12928 * 4)
__global__ __launch_bounds__(256, 1) void atom_post_kernel(
    const float* __restrict__ prop, const float* __restrict__ res0w,
    const float* __restrict__ w1, const float* __restrict__ b1,
    const float* __restrict__ w2, const float* __restrict__ b2,
    const float* __restrict__ wo, float* __restrict__ out, int d)
{
    extern __shared__ float sm[];
    float* bufA = sm;
    float* bufB = sm + 4352;
    float* sW   = sm + 8704;
    float* sB   = sm + 12800;
    float* sWo  = sm + 12864;

    const int tid = threadIdx.x;
    const int abase = blockIdx.x * 64;
    const int ar = tid >> 4, cr = tid & 15;

    float pn[4][4];
#pragma unroll
    for (int i = 0; i < 4; i++) { pn[i][0] = pn[i][1] = pn[i][2] = pn[i][3] = 0.f; }

    if (d == 0) {
        for (int i = tid; i < 1024; i += 256) sW[i] = res0w[i];
        for (int i = tid; i < 256; i += 256) {
            int a = i >> 2, seg = i & 3;
            float4 v = make_float4(0.f, 0.f, 0.f, 0.f);
            if (abase + a < NATOMS) v = ((const float4*)prop)[(abase + a) * 4 + seg];
            *(float4*)(bufB + a * 16 + seg * 4) = v;
        }
        __syncthreads();
        const float* A = bufB + ar * 4 * 16;
        const float* W = sW + cr * 4;
#pragma unroll
        for (int k4 = 0; k4 < 4; k4++) mm4(pn, A, 16, W, 64, k4);
    }

#pragma unroll
    for (int i = 0; i < 4; i++) {
        int a = abase + ar * 4 + i;
        float4 v = make_float4(0.f, 0.f, 0.f, 0.f);
        if (a < NATOMS) {
            float4 np = ((const float4*)g_newp)[a * 16 + cr];
            if (d == 0) {
                v.x = pn[i][0] + np.x; v.y = pn[i][1] + np.y;
                v.z = pn[i][2] + np.z; v.w = pn[i][3] + np.w;
            } else {
                float4 pv = ((const float4*)g_p)[a * 16 + cr];
                v.x = pv.x + np.x; v.y = pv.y + np.y;
                v.z = pv.z + np.z; v.w = pv.w + np.w;
            }
            ((float4*)g_p)[a * 16 + cr] = v;
        }
        *(float4*)(bufA + (ar * 4 + i) * 68 + cr * 4) = v;
    }
    __syncthreads();

    for (int i = tid; i < 4096; i += 256) sW[i] = w1[i];
    if (tid < 64) { sB[tid] = b1[tid]; sWo[tid] = wo[tid]; }
    __syncthreads();

    {
        float acc[4][4];
#pragma unroll
        for (int i = 0; i < 4; i++) { acc[i][0] = acc[i][1] = acc[i][2] = acc[i][3] = 0.f; }
        const float* A = bufA + ar * 4 * 68;
        const float* W = sW + cr * 4;
#pragma unroll 4
        for (int k4 = 0; k4 < 16; k4++) mm4(acc, A, 68, W, 64, k4);
        float4 bv = *(const float4*)(sB + cr * 4);
#pragma unroll
        for (int i = 0; i < 4; i++) {
            float4 v;
            v.x = tfast(acc[i][0] + bv.x); v.y = tfast(acc[i][1] + bv.y);
            v.z = tfast(acc[i][2] + bv.z); v.w = tfast(acc[i][3] + bv.w);
            *(float4*)(bufB + (ar * 4 + i) * 68 + cr * 4) = v;
        }
    }
    __syncthreads();
    for (int i = tid; i < 4096; i += 256) sW[i] = w2[i];
    if (tid < 64) sB[tid] = b2[tid];
    __syncthreads();

    {
        float acc[4][4];
#pragma unroll
        for (int i = 0; i < 4; i++) { acc[i][0] = acc[i][1] = acc[i][2] = acc[i][3] = 0.f; }
        const float* A = bufB + ar * 4 * 68;
        const float* W = sW + cr * 4;
#pragma unroll 4
        for (int k4 = 0; k4 < 16; k4++) mm4(acc, A, 68, W, 64, k4);
        float4 bv = *(const float4*)(sB + cr * 4);
#pragma unroll
        for (int i = 0; i < 4; i++) {
            float4 v;
            v.x = tfast(acc[i][0] + bv.x); v.y = tfast(acc[i][1] + bv.y);
            v.z = tfast(acc[i][2] + bv.z); v.w = tfast(acc[i][3] + bv.w);
            *(float4*)(bufA + (ar * 4 + i) * 68 + cr * 4) = v;
        }
    }
    __syncthreads();

    if (tid < 64) {
        int a = abase + tid;
        if (a < NATOMS) {
            float s = 0.f;
            const float* row = bufA + tid * 68;
#pragma unroll 8
            for (int c = 0; c < 64; c++) s = fmaf(row[c], sWo[c], s);
            out[a] = (d == 0) ? s : (out[a] + s);
        }
    }
}

// ---------------------------------------------------------------------------
extern "C" void kernel_launch(void* const* d_in, const int* in_sizes, int n_in,
                              void* d_out, int out_size) {
    const int*   ind2   = (const int*)d_in[0];
    const float* prop   = (const float*)d_in[1];
    const float* basis  = (const float*)d_in[2];
    const float* pp0_w1 = (const float*)d_in[3];
    const float* pp0_b1 = (const float*)d_in[4];
    const float* pp_w1  = (const float*)d_in[5];
    const float* pp_b1  = (const float*)d_in[6];
    const float* pp_w2  = (const float*)d_in[7];
    const float* pp_b2  = (const float*)d_in[8];
    const float* pi_w1  = (const float*)d_in[9];
    const float* pi_b1  = (const float*)d_in[10];
    const float* pi_w2  = (const float*)d_in[11];
    const float* pi_b2  = (const float*)d_in[12];
    const float* ii_w1  = (const float*)d_in[13];
    const float* ii_w2  = (const float*)d_in[14];
    const float* res0   = (const float*)d_in[15];
    const float* ow1    = (const float*)d_in[16];
    const float* ob1    = (const float*)d_in[17];
    const float* ow2    = (const float*)d_in[18];
    const float* ob2    = (const float*)d_in[19];
    const float* owo    = (const float*)d_in[20];
    float* out = (float*)d_out;

    static bool inited = false;
    if (!inited) {
        cudaFuncSetAttribute(pairA, cudaFuncAttributeMaxDynamicSharedMemorySize, A_SMEM_BYTES);
        cudaFuncSetAttribute(pairB, cudaFuncAttributeMaxDynamicSharedMemorySize, B_SMEM_BYTES);
        cudaFuncSetAttribute(atom_pre_kernel, cudaFuncAttributeMaxDynamicSharedMemorySize, PRE_SMEM_BYTES);
        cudaFuncSetAttribute(atom_post_kernel, cudaFuncAttributeMaxDynamicSharedMemorySize, POST_SMEM_BYTES);
        inited = true;
    }

    const int atom_blocks = (NATOMS + 63) / 64;

    for (int d = 0; d < 4; d++) {
        const float* w1 = (d == 0) ? pp0_w1 : pp_w1 + (d - 1) * 4096;
        const float* b1 = (d == 0) ? pp0_b1 : pp_b1 + (d - 1) * 64;
        prep_kernel<<<16, 256>>>(pi_w2 + d * 16384, ii_w1 + d * 4096, ii_w2 + d * 4096);
        atom_pre_kernel<<<atom_blocks, 256, PRE_SMEM_BYTES>>>(
            prop, d, w1, b1, pp_w2 + d * 4096, pp_b2 + d * 64,
            pi_w1 + d * 8192, pi_b1 + d * 64);
        pairA<<<444, 256, A_SMEM_BYTES>>>(ind2, basis, pi_b2 + d * 256);
        pairB<<<444, 256, B_SMEM_BYTES>>>(ind2);
        atom_post_kernel<<<atom_blocks, 256, POST_SMEM_BYTES>>>(
            prop, res0,
            ow1 + d * 4096, ob1 + d * 64,
            ow2 + d * 4096, ob2 + d * 64,
            owo + d * 64, out, d);
    }
}

// round 17
// speedup vs baseline: 1.0352x; 1.0352x over previous
#include <cuda_runtime.h>
#include <cuda_fp16.h>
#include <cstdint>

#define NATOMS 25000
#define NPAIRS 500000
#define NBLKA 7813
#define NBLKB 3907

__device__ __align__(16) float g_p[NATOMS * 64];
__device__ __align__(16) float g_newp[NATOMS * 64];
__device__ __align__(16) float g_u[NATOMS * 64];
__device__ __align__(16) float g_v[NATOMS * 64];
__device__ __align__(16) uint32_t g_w2H[8192], g_w2L[8192];
__device__ __align__(16) uint32_t g_wi1H[2048], g_wi1L[2048];
__device__ __align__(16) uint32_t g_wi2H[2048], g_wi2L[2048];
__device__ __align__(16) uint32_t g_intH[(NPAIRS + 128) * 32];
__device__ __align__(16) uint32_t g_intL[(NPAIRS + 128) * 32];

// R9-proven tanh: 1 - 2/(e^{2x}+1) via __expf + approx divide (~1e-6 rel err)
__device__ __forceinline__ float tfast(float x) {
    x = fminf(fmaxf(x, -15.f), 15.f);
    float e = __expf(2.f * x);
    return 1.f - __fdividef(2.f, e + 1.f);
}

__device__ __forceinline__ void split2(float x0, float x1, uint32_t& H, uint32_t& L) {
    __half h0 = __float2half_rn(x0), h1 = __float2half_rn(x1);
    float r0 = x0 - __half2float(h0);
    float r1 = x1 - __half2float(h1);
    __half2 hh = __halves2half2(h0, h1);
    __half2 ll = __halves2half2(__float2half_rn(r0), __float2half_rn(r1));
    H = *reinterpret_cast<uint32_t*>(&hh);
    L = *reinterpret_cast<uint32_t*>(&ll);
}

__device__ __forceinline__ void mma16(float* d, uint32_t a0, uint32_t a1, uint32_t a2,
                                      uint32_t a3, uint32_t b0, uint32_t b1) {
    asm volatile("mma.sync.aligned.m16n8k16.row.col.f32.f16.f16.f32 "
        "{%0,%1,%2,%3}, {%4,%5,%6,%7}, {%8,%9}, {%0,%1,%2,%3};"
        : "+f"(d[0]), "+f"(d[1]), "+f"(d[2]), "+f"(d[3])
        : "r"(a0), "r"(a1), "r"(a2), "r"(a3), "r"(b0), "r"(b1));
}

__device__ __forceinline__ void red4(float* p, float a, float b, float c, float d) {
    asm volatile("red.global.add.v4.f32 [%0], {%1,%2,%3,%4};"
        :: "l"(p), "f"(a), "f"(b), "f"(c), "f"(d) : "memory");
}

// 3-term fp16 warp GEMM: 32 rows x 32 cols, K=16*KC.
// A operands MUST be smem; W may be smem or global (warp-uniform 8B loads).
template<int KC>
__device__ __forceinline__ void gemm16(const uint32_t* __restrict__ AH, const uint32_t* __restrict__ AL,
        const uint32_t* __restrict__ WH, const uint32_t* __restrict__ WL,
        int r0, int tileBase, int lane, float acc[2][4][4])
{
    const int tig = lane & 3, gid = lane >> 2;
    const int sw = gid << 2;
#pragma unroll
    for (int kc = 0; kc < KC; kc++) {
        int k0 = (kc * 8 + tig) ^ sw;
        int k1 = (kc * 8 + tig + 4) ^ sw;
        uint32_t ah[2][4], al[2][4];
#pragma unroll
        for (int mt = 0; mt < 2; mt++) {
            const uint32_t* bh = AH + (r0 + mt * 16 + gid) * 32;
            const uint32_t* bl = AL + (r0 + mt * 16 + gid) * 32;
            ah[mt][0] = bh[k0]; ah[mt][1] = bh[256 + k0];
            ah[mt][2] = bh[k1]; ah[mt][3] = bh[256 + k1];
            al[mt][0] = bl[k0]; al[mt][1] = bl[256 + k0];
            al[mt][2] = bl[k1]; al[mt][3] = bl[256 + k1];
        }
#pragma unroll
        for (int nt = 0; nt < 4; nt++) {
            int wi = ((tileBase + nt) * KC + kc) * 64 + lane * 2;
            uint2 bh = *(const uint2*)(WH + wi);
            uint2 bl = *(const uint2*)(WL + wi);
#pragma unroll
            for (int mt = 0; mt < 2; mt++) {
                mma16(acc[mt][nt], ah[mt][0], ah[mt][1], ah[mt][2], ah[mt][3], bh.x, bh.y);
                mma16(acc[mt][nt], ah[mt][0], ah[mt][1], ah[mt][2], ah[mt][3], bl.x, bl.y);
                mma16(acc[mt][nt], al[mt][0], al[mt][1], al[mt][2], al[mt][3], bh.x, bh.y);
            }
        }
    }
}

// ---------------------------------------------------------------------------
__global__ void prep_kernel(const float* __restrict__ w2,
                            const float* __restrict__ wi1, const float* __restrict__ wi2) {
    int tid = blockIdx.x * blockDim.x + threadIdx.x;
    int stride = gridDim.x * blockDim.x;
    for (int idx = tid; idx < 4096; idx += stride) {
        int lane = idx & 31, kc = (idx >> 5) & 3, t = idx >> 7;
        int n = t * 8 + (lane >> 2);
        int k0 = kc * 16 + 2 * (lane & 3);
        int o = (t * 4 + kc) * 64 + lane * 2;
        uint32_t h, l;
        split2(w2[k0 * 256 + n], w2[(k0 + 1) * 256 + n], h, l);
        g_w2H[o] = h; g_w2L[o] = l;
        split2(w2[(k0 + 8) * 256 + n], w2[(k0 + 9) * 256 + n], h, l);
        g_w2H[o + 1] = h; g_w2L[o + 1] = l;
    }
    for (int idx = tid; idx < 1024; idx += stride) {
        int lane = idx & 31, kc = (idx >> 5) & 3, t = idx >> 7;
        int n = t * 8 + (lane >> 2);
        int k0 = kc * 16 + 2 * (lane & 3);
        int o = (t * 4 + kc) * 64 + lane * 2;
        uint32_t h, l;
        split2(wi1[k0 * 64 + n], wi1[(k0 + 1) * 64 + n], h, l);
        g_wi1H[o] = h; g_wi1L[o] = l;
        split2(wi1[(k0 + 8) * 64 + n], wi1[(k0 + 9) * 64 + n], h, l);
        g_wi1H[o + 1] = h; g_wi1L[o + 1] = l;
        split2(wi2[k0 * 64 + n], wi2[(k0 + 1) * 64 + n], h, l);
        g_wi2H[o] = h; g_wi2L[o] = l;
        split2(wi2[(k0 + 8) * 64 + n], wi2[(k0 + 9) * 64 + n], h, l);
        g_wi2H[o + 1] = h; g_wi2L[o + 1] = l;
    }
    for (int i = tid; i < 4096; i += stride) {
        g_intH[NPAIRS * 32 + i] = 0;
        g_intL[NPAIRS * 32 + i] = 0;
    }
}

// ---------------------------------------------------------------------------
// pairA: persistent, 64 pairs/iter, 3 CTAs/SM (R9-exact).
// ---------------------------------------------------------------------------
#define A_W2H  0        // 8192 words
#define A_WW1H 8192     // 2048
#define A_WW1L 10240    // 2048
#define A_INTH 12288    // 2048
#define A_INTL 14336    // 2048
#define A_BAS  16384    // 256 floats
#define A_B2   16640    // 256 floats
#define A_SMEM_BYTES (16896 * 4)

__global__ __launch_bounds__(256, 3) void pairA(
    const int* __restrict__ ind2, const float* __restrict__ basis,
    const float* __restrict__ b2)
{
    extern __shared__ uint32_t smw[];
    float* smf = (float*)smw;
    const int tid = threadIdx.x;

    for (int i = tid; i < 2048; i += 256) ((uint4*)(smw + A_W2H))[i] = ((const uint4*)g_w2H)[i];
    if (tid < 128) { smf[A_B2 + tid] = b2[tid]; smf[A_B2 + 128 + tid] = b2[128 + tid]; }

    const int lane = tid & 31, w = tid >> 5;
    const int rg = w & 1, cg = w >> 1;
    const int r0 = rg * 32;
    const int tig = lane & 3, gid = lane >> 2;

    for (int blk = blockIdx.x; blk < NBLKA; blk += gridDim.x) {
        const int pairbase = blk * 64;
        __syncthreads();

        if (tid < 64) {
            int p = pairbase + tid;
            float4 bs = make_float4(0.f, 0.f, 0.f, 0.f);
            if (p < NPAIRS) bs = ((const float4*)basis)[p];
            ((float4*)(smf + A_BAS))[tid] = bs;
        }
#pragma unroll
        for (int r = 0; r < 8; r++) {
            int idx = tid + r * 256;
            int row = idx >> 5, kp = idx & 31;
            int gp = pairbase + row;
            float x0 = 0.f, x1 = 0.f;
            if (gp < NPAIRS) {
                int ai = ind2[2 * gp], aj = ind2[2 * gp + 1];
                float2 u = *(const float2*)&g_u[ai * 64 + 2 * kp];
                float2 v = *(const float2*)&g_v[aj * 64 + 2 * kp];
                x0 = tfast(u.x + v.x);
                x1 = tfast(u.y + v.y);
            }
            uint32_t H, L; split2(x0, x1, H, L);
            int o = row * 32 + (kp ^ ((row & 7) << 2));
            smw[A_WW1H + o] = H; smw[A_WW1L + o] = L;
        }
        __syncthreads();

        float4 bsv[4];
#pragma unroll
        for (int q = 0; q < 4; q++) bsv[q] = ((float4*)(smf + A_BAS))[r0 + gid + q * 8];
#pragma unroll 1
        for (int j = 0; j < 2; j++) {
            int g = cg + 4 * j;
            float acc[2][4][4];
#pragma unroll
            for (int a = 0; a < 2; a++)
#pragma unroll
                for (int b = 0; b < 4; b++)
#pragma unroll
                    for (int q = 0; q < 4; q++) acc[a][b][q] = 0.f;
            gemm16<4>(smw + A_WW1H, smw + A_WW1L,
                      smw + A_W2H, g_w2L, r0, g * 4, lane, acc);
#pragma unroll
            for (int mt = 0; mt < 2; mt++)
#pragma unroll
                for (int nt = 0; nt < 4; nt++) {
                    int c0 = g * 32 + nt * 8 + 2 * tig;
                    float b20 = smf[A_B2 + c0], b21 = smf[A_B2 + c0 + 1];
                    float4 bL = bsv[mt * 2], bH = bsv[mt * 2 + 1];
                    float cL0 = (tig & 1) ? bL.z : bL.x, cL1 = (tig & 1) ? bL.w : bL.y;
                    float cH0 = (tig & 1) ? bH.z : bH.x, cH1 = (tig & 1) ? bH.w : bH.y;
                    float pl = tfast(acc[mt][nt][0] + b20) * cL0 + tfast(acc[mt][nt][1] + b21) * cL1;
                    float ph = tfast(acc[mt][nt][2] + b20) * cH0 + tfast(acc[mt][nt][3] + b21) * cH1;
                    pl += __shfl_xor_sync(0xffffffffu, pl, 1);
                    ph += __shfl_xor_sync(0xffffffffu, ph, 1);
                    float pl2 = __shfl_xor_sync(0xffffffffu, pl, 2);
                    float ph2 = __shfl_xor_sync(0xffffffffu, ph, 2);
                    if (tig == 0) {
                        int kp = g * 4 + nt;
                        int rL = r0 + mt * 16 + gid, rH = rL + 8;
                        uint32_t H, L;
                        split2(pl, pl2, H, L);
                        int o = rL * 32 + (kp ^ (gid << 2));
                        smw[A_INTH + o] = H; smw[A_INTL + o] = L;
                        split2(ph, ph2, H, L);
                        o = rH * 32 + (kp ^ (gid << 2));
                        smw[A_INTH + o] = H; smw[A_INTL + o] = L;
                    }
                }
        }
        __syncthreads();
        for (int i = tid; i < 512; i += 256) {
            ((uint4*)(g_intH + pairbase * 32))[i] = ((uint4*)(smw + A_INTH))[i];
            ((uint4*)(g_intL + pairbase * 32))[i] = ((uint4*)(smw + A_INTL))[i];
        }
    }
}

// ---------------------------------------------------------------------------
// pairB: persistent, 128 pairs/iter, 3 CTAs/SM (R9-exact).
// ---------------------------------------------------------------------------
#define B_R0   0
#define B_WI1H 8704
#define B_WI1L 10752
#define B_WI2H 12800
#define B_WI2L 14848
#define B_IDX  16896
#define B_SMEM_BYTES (17024 * 4)

__global__ __launch_bounds__(256, 3) void pairB(const int* __restrict__ ind2)
{
    extern __shared__ uint32_t smw[];
    float* smf = (float*)smw;
    const int tid = threadIdx.x;

    for (int i = tid; i < 512; i += 256) {
        ((uint4*)(smw + B_WI1H))[i] = ((const uint4*)g_wi1H)[i];
        ((uint4*)(smw + B_WI1L))[i] = ((const uint4*)g_wi1L)[i];
        ((uint4*)(smw + B_WI2H))[i] = ((const uint4*)g_wi2H)[i];
        ((uint4*)(smw + B_WI2L))[i] = ((const uint4*)g_wi2L)[i];
    }

    const int lane = tid & 31, w = tid >> 5;
    const int rg = w & 3, cg = w >> 2;
    const int r0 = rg * 32;
    const int tig = lane & 3, gid = lane >> 2;

    for (int blk = blockIdx.x; blk < NBLKB; blk += gridDim.x) {
        const int pairbase = blk * 128;
        __syncthreads();

        for (int i = tid; i < 1024; i += 256) {
            ((uint4*)(smw + B_R0))[i] = ((const uint4*)(g_intH + pairbase * 32))[i];
            ((uint4*)(smw + B_R0 + 4096))[i] = ((const uint4*)(g_intL + pairbase * 32))[i];
        }
        if (tid < 128) {
            int p = pairbase + tid;
            ((int*)(smw + B_IDX))[tid] = (p < NPAIRS) ? ind2[2 * p] : -1;
        }
        __syncthreads();

        float acc[2][4][4];
#pragma unroll
        for (int a = 0; a < 2; a++)
#pragma unroll
            for (int b = 0; b < 4; b++)
#pragma unroll
                for (int q = 0; q < 4; q++) acc[a][b][q] = 0.f;
        gemm16<4>(smw + B_R0, smw + B_R0 + 4096, smw + B_WI1H, smw + B_WI1L, r0, cg * 4, lane, acc);
        __syncthreads();
#pragma unroll
        for (int mt = 0; mt < 2; mt++)
#pragma unroll
            for (int nt = 0; nt < 4; nt++) {
                int kp = cg * 16 + nt * 4 + tig;
                int rL = r0 + mt * 16 + gid, rH = rL + 8;
                uint32_t H, L;
                split2(tfast(acc[mt][nt][0]), tfast(acc[mt][nt][1]), H, L);
                int o = rL * 32 + (kp ^ (gid << 2));
                smw[B_R0 + o] = H; smw[B_R0 + 4096 + o] = L;
                split2(tfast(acc[mt][nt][2]), tfast(acc[mt][nt][3]), H, L);
                o = rH * 32 + (kp ^ (gid << 2));
                smw[B_R0 + o] = H; smw[B_R0 + 4096 + o] = L;
            }
        __syncthreads();

#pragma unroll
        for (int a = 0; a < 2; a++)
#pragma unroll
            for (int b = 0; b < 4; b++)
#pragma unroll
                for (int q = 0; q < 4; q++) acc[a][b][q] = 0.f;
        gemm16<4>(smw + B_R0, smw + B_R0 + 4096, smw + B_WI2H, smw + B_WI2L, r0, cg * 4, lane, acc);
        __syncthreads();
#pragma unroll
        for (int mt = 0; mt < 2; mt++)
#pragma unroll
            for (int nt = 0; nt < 4; nt++) {
                int c0 = cg * 32 + nt * 8 + 2 * tig;
                int rL = r0 + mt * 16 + gid, rH = rL + 8;
                float2 v;
                v.x = tfast(acc[mt][nt][0]); v.y = tfast(acc[mt][nt][1]);
                *(float2*)&smf[rL * 68 + c0] = v;
                v.x = tfast(acc[mt][nt][2]); v.y = tfast(acc[mt][nt][3]);
                *(float2*)&smf[rH * 68 + c0] = v;
            }
        __syncthreads();

        const int* idxI = (const int*)(smw + B_IDX);
#pragma unroll
        for (int r = 0; r < 8; r++) {
            int i = tid + r * 256;
            int row = i >> 4, seg = i & 15;
            int a = idxI[row];
            if (a >= 0) {
                float4 v = *(float4*)&smf[row * 68 + seg * 4];
                red4(g_newp + a * 64 + seg * 4, v.x, v.y, v.z, v.w);
            }
        }
    }
}

// ---------------------------------------------------------------------------
__device__ __forceinline__ void mm4(float acc[4][4], const float* __restrict__ A, int lda,
                                    const float* __restrict__ W, int ldw, int k4) {
    float4 w0 = *(const float4*)(W + (k4 * 4 + 0) * ldw);
    float4 w1 = *(const float4*)(W + (k4 * 4 + 1) * ldw);
    float4 w2 = *(const float4*)(W + (k4 * 4 + 2) * ldw);
    float4 w3 = *(const float4*)(W + (k4 * 4 + 3) * ldw);
#pragma unroll
    for (int i = 0; i < 4; i++) {
        float4 a = *(const float4*)(A + i * lda + k4 * 4);
        acc[i][0] = fmaf(a.x, w0.x, fmaf(a.y, w1.x, fmaf(a.z, w2.x, fmaf(a.w, w3.x, acc[i][0]))));
        acc[i][1] = fmaf(a.x, w0.y, fmaf(a.y, w1.y, fmaf(a.z, w2.y, fmaf(a.w, w3.y, acc[i][1]))));
        acc[i][2] = fmaf(a.x, w0.z, fmaf(a.y, w1.z, fmaf(a.z, w2.z, fmaf(a.w, w3.z, acc[i][2]))));
        acc[i][3] = fmaf(a.x, w0.w, fmaf(a.y, w1.w, fmaf(a.z, w2.w, fmaf(a.w, w3.w, acc[i][3]))));
    }
}

// ---------------------------------------------------------------------------
// atom_pre: only used for depth 0 (p = prop, K0 = 16). Computes u/v, zeroes newp.
// ---------------------------------------------------------------------------
#define PRE_SMEM_BYTES (12416 * 4)
__global__ __launch_bounds__(256, 1) void atom_pre_kernel(
    const float* __restrict__ prop,
    const float* __restrict__ w1, const float* __restrict__ b1,
    const float* __restrict__ w2, const float* __restrict__ b2,
    const float* __restrict__ piw1, const float* __restrict__ pib1)
{
    extern __shared__ float sm[];
    float* sSrc = sm;
    float* sW   = sm + 4096;
    float* sH   = sm + 8192;
    float* sB   = sm + 12288;
    float* sB1  = sm + 12352;

    const int tid = threadIdx.x;
    const int abase = blockIdx.x * 64;

    for (int i = tid; i < 1024; i += 256) sW[i] = w1[i];   // K0=16
    if (tid < 64) { sB[tid] = b1[tid]; sB1[tid] = pib1[tid]; }
    for (int i = tid; i < 256; i += 256) {
        int a = i >> 2, seg = i & 3;
        float4 v = make_float4(0.f, 0.f, 0.f, 0.f);
        if (abase + a < NATOMS) v = ((const float4*)prop)[(abase + a) * 4 + seg];
        *(float4*)(sSrc + a * 64 + seg * 4) = v;
    }
    for (int i = tid; i < 1024; i += 256) {
        int a = i >> 4;
        if (abase + a < NATOMS)
            ((float4*)g_newp)[(abase + a) * 16 + (i & 15)] = make_float4(0.f, 0.f, 0.f, 0.f);
    }
    __syncthreads();

    const int ar = tid >> 4, cr = tid & 15;
    {
        float acc[4][4];
#pragma unroll
        for (int i = 0; i < 4; i++) { acc[i][0] = acc[i][1] = acc[i][2] = acc[i][3] = 0.f; }
        const float* A = sSrc + ar * 4 * 64;
        const float* W = sW + cr * 4;
        for (int k4 = 0; k4 < 4; k4++) mm4(acc, A, 64, W, 64, k4);
        float4 bv = *(const float4*)(sB + cr * 4);
#pragma unroll
        for (int i = 0; i < 4; i++) {
            float4 v;
            v.x = tfast(acc[i][0] + bv.x); v.y = tfast(acc[i][1] + bv.y);
            v.z = tfast(acc[i][2] + bv.z); v.w = tfast(acc[i][3] + bv.w);
            *(float4*)(sH + (ar * 4 + i) * 64 + cr * 4) = v;
        }
    }
    __syncthreads();
    for (int i = tid; i < 4096; i += 256) sW[i] = w2[i];
    if (tid < 64) sB[tid] = b2[tid];
    __syncthreads();
    {
        float acc[4][4];
#pragma unroll
        for (int i = 0; i < 4; i++) { acc[i][0] = acc[i][1] = acc[i][2] = acc[i][3] = 0.f; }
        const float* A = sH + ar * 4 * 64;
        const float* W = sW + cr * 4;
#pragma unroll 4
        for (int k4 = 0; k4 < 16; k4++) mm4(acc, A, 64, W, 64, k4);
        float4 bv = *(const float4*)(sB + cr * 4);
#pragma unroll
        for (int i = 0; i < 4; i++) {
            float4 v;
            v.x = tfast(acc[i][0] + bv.x); v.y = tfast(acc[i][1] + bv.y);
            v.z = tfast(acc[i][2] + bv.z); v.w = tfast(acc[i][3] + bv.w);
            *(float4*)(sSrc + (ar * 4 + i) * 64 + cr * 4) = v;   // h
        }
    }
    __syncthreads();

    for (int i = tid; i < 4096; i += 256) sW[i] = piw1[i];
    __syncthreads();
    {
        float acc[4][4];
#pragma unroll
        for (int i = 0; i < 4; i++) { acc[i][0] = acc[i][1] = acc[i][2] = acc[i][3] = 0.f; }
        const float* A = sSrc + ar * 4 * 64;
        const float* W = sW + cr * 4;
#pragma unroll 4
        for (int k4 = 0; k4 < 16; k4++) mm4(acc, A, 64, W, 64, k4);
        float4 bv = *(const float4*)(sB1 + cr * 4);
#pragma unroll
        for (int i = 0; i < 4; i++) {
            int a = abase + ar * 4 + i;
            if (a < NATOMS) {
                float4 v;
                v.x = acc[i][0] + bv.x; v.y = acc[i][1] + bv.y;
                v.z = acc[i][2] + bv.z; v.w = acc[i][3] + bv.w;
                ((float4*)g_u)[a * 16 + cr] = v;
            }
        }
    }
    __syncthreads();

    for (int i = tid; i < 4096; i += 256) sW[i] = piw1[4096 + i];
    __syncthreads();
    {
        float acc[4][4];
#pragma unroll
        for (int i = 0; i < 4; i++) { acc[i][0] = acc[i][1] = acc[i][2] = acc[i][3] = 0.f; }
        const float* A = sSrc + ar * 4 * 64;
        const float* W = sW + cr * 4;
#pragma unroll 4
        for (int k4 = 0; k4 < 16; k4++) mm4(acc, A, 64, W, 64, k4);
#pragma unroll
        for (int i = 0; i < 4; i++) {
            int a = abase + ar * 4 + i;
            if (a < NATOMS) {
                float4 v = make_float4(acc[i][0], acc[i][1], acc[i][2], acc[i][3]);
                ((float4*)g_v)[a * 16 + cr] = v;
            }
        }
    }
}

// ---------------------------------------------------------------------------
// atom_fused: post(d) + pre(d+1) in one kernel.
// p-update -> out head (o2 in regs, shfl-tree dot) -> next-depth h/u/v -> zero newp.
// ---------------------------------------------------------------------------
#define FUSE_SMEM_BYTES (12992 * 4)
__global__ __launch_bounds__(256, 1) void atom_fused(
    const float* __restrict__ prop, const float* __restrict__ res0w,
    const float* __restrict__ ow1, const float* __restrict__ ob1,
    const float* __restrict__ ow2, const float* __restrict__ ob2,
    const float* __restrict__ owo, float* __restrict__ out, int d,
    const float* __restrict__ nw1, const float* __restrict__ nb1,
    const float* __restrict__ nw2, const float* __restrict__ nb2,
    const float* __restrict__ npiw1, const float* __restrict__ npib1, int do_pre)
{
    extern __shared__ float sm[];
    float* bufA = sm;            // 64 x 68
    float* bufB = sm + 4352;     // 64 x 68
    float* sW   = sm + 8704;     // 4096
    float* sB   = sm + 12800;    // 64
    float* sB1  = sm + 12864;    // 64
    float* sWo  = sm + 12928;    // 64

    const int tid = threadIdx.x;
    const int abase = blockIdx.x * 64;
    const int ar = tid >> 4, cr = tid & 15;
    const int lane = tid & 31;

    float pn[4][4];
#pragma unroll
    for (int i = 0; i < 4; i++) { pn[i][0] = pn[i][1] = pn[i][2] = pn[i][3] = 0.f; }

    if (d == 0) {
        for (int i = tid; i < 1024; i += 256) sW[i] = res0w[i];
        for (int i = tid; i < 256; i += 256) {
            int a = i >> 2, seg = i & 3;
            float4 v = make_float4(0.f, 0.f, 0.f, 0.f);
            if (abase + a < NATOMS) v = ((const float4*)prop)[(abase + a) * 4 + seg];
            *(float4*)(bufB + a * 16 + seg * 4) = v;
        }
        __syncthreads();
        const float* A = bufB + ar * 4 * 16;
        const float* W = sW + cr * 4;
#pragma unroll
        for (int k4 = 0; k4 < 4; k4++) mm4(pn, A, 16, W, 64, k4);
    }

    // pnew = prev + newp -> g_p and bufA
#pragma unroll
    for (int i = 0; i < 4; i++) {
        int a = abase + ar * 4 + i;
        float4 v = make_float4(0.f, 0.f, 0.f, 0.f);
        if (a < NATOMS) {
            float4 np = ((const float4*)g_newp)[a * 16 + cr];
            if (d == 0) {
                v.x = pn[i][0] + np.x; v.y = pn[i][1] + np.y;
                v.z = pn[i][2] + np.z; v.w = pn[i][3] + np.w;
            } else {
                float4 pv = ((const float4*)g_p)[a * 16 + cr];
                v.x = pv.x + np.x; v.y = pv.y + np.y;
                v.z = pv.z + np.z; v.w = pv.w + np.w;
            }
            ((float4*)g_p)[a * 16 + cr] = v;
        }
        *(float4*)(bufA + (ar * 4 + i) * 68 + cr * 4) = v;
    }
    __syncthreads();

    // zero newp for next depth (reads above complete)
    if (do_pre) {
        for (int i = tid; i < 1024; i += 256) {
            int a = i >> 4;
            if (abase + a < NATOMS)
                ((float4*)g_newp)[(abase + a) * 16 + (i & 15)] = make_float4(0.f, 0.f, 0.f, 0.f);
        }
    }

    for (int i = tid; i < 4096; i += 256) sW[i] = ow1[i];
    if (tid < 64) { sB[tid] = ob1[tid]; sWo[tid] = owo[tid]; }
    __syncthreads();

    // o1 = tanh(pnew @ ow1 + ob1) -> bufB
    {
        float acc[4][4];
#pragma unroll
        for (int i = 0; i < 4; i++) { acc[i][0] = acc[i][1] = acc[i][2] = acc[i][3] = 0.f; }
        const float* A = bufA + ar * 4 * 68;
        const float* W = sW + cr * 4;
#pragma unroll 4
        for (int k4 = 0; k4 < 16; k4++) mm4(acc, A, 68, W, 64, k4);
        float4 bv = *(const float4*)(sB + cr * 4);
#pragma unroll
        for (int i = 0; i < 4; i++) {
            float4 v;
            v.x = tfast(acc[i][0] + bv.x); v.y = tfast(acc[i][1] + bv.y);
            v.z = tfast(acc[i][2] + bv.z); v.w = tfast(acc[i][3] + bv.w);
            *(float4*)(bufB + (ar * 4 + i) * 68 + cr * 4) = v;
        }
    }
    __syncthreads();
    for (int i = tid; i < 4096; i += 256) sW[i] = ow2[i];
    if (tid < 64) sB[tid] = ob2[tid];
    __syncthreads();

    // o2 = tanh(o1 @ ow2 + ob2) in regs; out += o2 @ owo via 16-lane shfl tree
    {
        float acc[4][4];
#pragma unroll
        for (int i = 0; i < 4; i++) { acc[i][0] = acc[i][1] = acc[i][2] = acc[i][3] = 0.f; }
        const float* A = bufB + ar * 4 * 68;
        const float* W = sW + cr * 4;
#pragma unroll 4
        for (int k4 = 0; k4 < 16; k4++) mm4(acc, A, 68, W, 64, k4);
        float4 bv = *(const float4*)(sB + cr * 4);
        float4 wv = *(const float4*)(sWo + cr * 4);
#pragma unroll
        for (int i = 0; i < 4; i++) {
            float s = tfast(acc[i][0] + bv.x) * wv.x
                    + tfast(acc[i][1] + bv.y) * wv.y
                    + tfast(acc[i][2] + bv.z) * wv.z
                    + tfast(acc[i][3] + bv.w) * wv.w;
            s += __shfl_xor_sync(0xffffffffu, s, 1);
            s += __shfl_xor_sync(0xffffffffu, s, 2);
            s += __shfl_xor_sync(0xffffffffu, s, 4);
            s += __shfl_xor_sync(0xffffffffu, s, 8);
            if ((lane & 15) == 0) {
                int a = abase + ar * 4 + i;
                if (a < NATOMS) out[a] = (d == 0) ? s : (out[a] + s);
            }
        }
    }

    if (!do_pre) return;
    __syncthreads();

    // ---- pre for depth d+1: h1 = tanh(pnew @ nw1 + nb1) ----
    for (int i = tid; i < 4096; i += 256) sW[i] = nw1[i];
    if (tid < 64) { sB[tid] = nb1[tid]; sB1[tid] = npib1[tid]; }
    __syncthreads();
    {
        float acc[4][4];
#pragma unroll
        for (int i = 0; i < 4; i++) { acc[i][0] = acc[i][1] = acc[i][2] = acc[i][3] = 0.f; }
        const float* A = bufA + ar * 4 * 68;
        const float* W = sW + cr * 4;
#pragma unroll 4
        for (int k4 = 0; k4 < 16; k4++) mm4(acc, A, 68, W, 64, k4);
        float4 bv = *(const float4*)(sB + cr * 4);
#pragma unroll
        for (int i = 0; i < 4; i++) {
            float4 v;
            v.x = tfast(acc[i][0] + bv.x); v.y = tfast(acc[i][1] + bv.y);
            v.z = tfast(acc[i][2] + bv.z); v.w = tfast(acc[i][3] + bv.w);
            *(float4*)(bufB + (ar * 4 + i) * 68 + cr * 4) = v;
        }
    }
    __syncthreads();
    for (int i = tid; i < 4096; i += 256) sW[i] = nw2[i];
    if (tid < 64) sB[tid] = nb2[tid];
    __syncthreads();

    // h = tanh(h1 @ nw2 + nb2) -> bufA (pnew dead)
    {
        float acc[4][4];
#pragma unroll
        for (int i = 0; i < 4; i++) { acc[i][0] = acc[i][1] = acc[i][2] = acc[i][3] = 0.f; }
        const float* A = bufB + ar * 4 * 68;
        const float* W = sW + cr * 4;
#pragma unroll 4
        for (int k4 = 0; k4 < 16; k4++) mm4(acc, A, 68, W, 64, k4);
        float4 bv = *(const float4*)(sB + cr * 4);
#pragma unroll
        for (int i = 0; i < 4; i++) {
            float4 v;
            v.x = tfast(acc[i][0] + bv.x); v.y = tfast(acc[i][1] + bv.y);
            v.z = tfast(acc[i][2] + bv.z); v.w = tfast(acc[i][3] + bv.w);
            *(float4*)(bufA + (ar * 4 + i) * 68 + cr * 4) = v;
        }
    }
    __syncthreads();

    // u = h @ npiw1_top + npib1
    for (int i = tid; i < 4096; i += 256) sW[i] = npiw1[i];
    __syncthreads();
    {
        float acc[4][4];
#pragma unroll
        for (int i = 0; i < 4; i++) { acc[i][0] = acc[i][1] = acc[i][2] = acc[i][3] = 0.f; }
        const float* A = bufA + ar * 4 * 68;
        const float* W = sW + cr * 4;
#pragma unroll 4
        for (int k4 = 0; k4 < 16; k4++) mm4(acc, A, 68, W, 64, k4);
        float4 bv = *(const float4*)(sB1 + cr * 4);
#pragma unroll
        for (int i = 0; i < 4; i++) {
            int a = abase + ar * 4 + i;
            if (a < NATOMS) {
                float4 v;
                v.x = acc[i][0] + bv.x; v.y = acc[i][1] + bv.y;
                v.z = acc[i][2] + bv.z; v.w = acc[i][3] + bv.w;
                ((float4*)g_u)[a * 16 + cr] = v;
            }
        }
    }
    __syncthreads();

    // v = h @ npiw1_bot
    for (int i = tid; i < 4096; i += 256) sW[i] = npiw1[4096 + i];
    __syncthreads();
    {
        float acc[4][4];
#pragma unroll
        for (int i = 0; i < 4; i++) { acc[i][0] = acc[i][1] = acc[i][2] = acc[i][3] = 0.f; }
        const float* A = bufA + ar * 4 * 68;
        const float* W = sW + cr * 4;
#pragma unroll 4
        for (int k4 = 0; k4 < 16; k4++) mm4(acc, A, 68, W, 64, k4);
#pragma unroll
        for (int i = 0; i < 4; i++) {
            int a = abase + ar * 4 + i;
            if (a < NATOMS) {
                float4 v = make_float4(acc[i][0], acc[i][1], acc[i][2], acc[i][3]);
                ((float4*)g_v)[a * 16 + cr] = v;
            }
        }
    }
}

// ---------------------------------------------------------------------------
extern "C" void kernel_launch(void* const* d_in, const int* in_sizes, int n_in,
                              void* d_out, int out_size) {
    const int*   ind2   = (const int*)d_in[0];
    const float* prop   = (const float*)d_in[1];
    const float* basis  = (const float*)d_in[2];
    const float* pp0_w1 = (const float*)d_in[3];
    const float* pp0_b1 = (const float*)d_in[4];
    const float* pp_w1  = (const float*)d_in[5];
    const float* pp_b1  = (const float*)d_in[6];
    const float* pp_w2  = (const float*)d_in[7];
    const float* pp_b2  = (const float*)d_in[8];
    const float* pi_w1  = (const float*)d_in[9];
    const float* pi_b1  = (const float*)d_in[10];
    const float* pi_w2  = (const float*)d_in[11];
    const float* pi_b2  = (const float*)d_in[12];
    const float* ii_w1  = (const float*)d_in[13];
    const float* ii_w2  = (const float*)d_in[14];
    const float* res0   = (const float*)d_in[15];
    const float* ow1    = (const float*)d_in[16];
    const float* ob1    = (const float*)d_in[17];
    const float* ow2    = (const float*)d_in[18];
    const float* ob2    = (const float*)d_in[19];
    const float* owo    = (const float*)d_in[20];
    float* out = (float*)d_out;

    static bool inited = false;
    if (!inited) {
        cudaFuncSetAttribute(pairA, cudaFuncAttributeMaxDynamicSharedMemorySize, A_SMEM_BYTES);
        cudaFuncSetAttribute(pairB, cudaFuncAttributeMaxDynamicSharedMemorySize, B_SMEM_BYTES);
        cudaFuncSetAttribute(atom_pre_kernel, cudaFuncAttributeMaxDynamicSharedMemorySize, PRE_SMEM_BYTES);
        cudaFuncSetAttribute(atom_fused, cudaFuncAttributeMaxDynamicSharedMemorySize, FUSE_SMEM_BYTES);
        inited = true;
    }

    const int atom_blocks = (NATOMS + 63) / 64;

    for (int d = 0; d < 4; d++) {
        prep_kernel<<<16, 256>>>(pi_w2 + d * 16384, ii_w1 + d * 4096, ii_w2 + d * 4096);
        if (d == 0) {
            atom_pre_kernel<<<atom_blocks, 256, PRE_SMEM_BYTES>>>(
                prop, pp0_w1, pp0_b1, pp_w2, pp_b2, pi_w1, pi_b1);
        }
        pairA<<<456, 256, A_SMEM_BYTES>>>(ind2, basis, pi_b2 + d * 256);
        pairB<<<456, 256, B_SMEM_BYTES>>>(ind2);
        int do_pre = (d < 3) ? 1 : 0;
        atom_fused<<<atom_blocks, 256, FUSE_SMEM_BYTES>>>(
            prop, res0,
            ow1 + d * 4096, ob1 + d * 64, ow2 + d * 4096, ob2 + d * 64,
            owo + d * 64, out, d,
            pp_w1 + d * 4096, pp_b1 + d * 64,
            pp_w2 + (do_pre ? (d + 1) : 0) * 4096, pp_b2 + (do_pre ? (d + 1) : 0) * 64,
            pi_w1 + (do_pre ? (d + 1) : 0) * 8192, pi_b1 + (do_pre ? (d + 1) : 0) * 64,
            do_pre);
    }
}